// round 7
// baseline (speedup 1.0000x reference)
#include <cuda_runtime.h>
#include <cstdint>

#define NN   512
#define HDIM 128
#define NH   8
#define MDIM 256
#define TI   8
#define TJ   16
#define EG   128     // edges per tile = TI*TJ
#define JS   4       // j splits
#define NTHREADS 512
#define SAPAD 260    // padded row stride for sA (conflict-free HMMA A loads: 4g+tg)
#define SATPAD 130   // transposed buffer stride (aliased onto sA; 256*130 <= 128*260)
#define SWPAD 264    // padded row stride for sW (conflict-free HMMA B loads: 8tg+g)
#define KSTAGE 32    // weight rows staged per sync

// ---- scratch (device globals; no allocation allowed) ----
__device__ float g_A[NN * MDIM];                 // hc @ We0[8:200]
__device__ float g_B[NN * MDIM];                 // hc @ We0[200:392]
__device__ float g_mi_part[JS * NN * MDIM];     // partial m_i per j-split
__device__ float g_shift_part[JS * NN * NH * 3];

__device__ __forceinline__ float siluf(float v) { return v / (1.0f + __expf(-v)); }
__device__ __forceinline__ float sigmf(float v) { return 1.0f / (1.0f + __expf(-v)); }

__device__ __forceinline__ uint32_t f2tf32(float v) {
    uint32_t r;
    asm("cvt.rna.tf32.f32 %0, %1;" : "=r"(r) : "f"(v));
    return r;
}
__device__ __forceinline__ float tf32r(float v) { return __uint_as_float(f2tf32(v)); }

__device__ __forceinline__ void mma_tf32(float* d,
    uint32_t a0, uint32_t a1, uint32_t a2, uint32_t a3,
    uint32_t b0, uint32_t b1)
{
    asm volatile(
        "mma.sync.aligned.m16n8k8.row.col.f32.tf32.tf32.f32 "
        "{%0,%1,%2,%3}, {%4,%5,%6,%7}, {%8,%9}, {%0,%1,%2,%3};\n"
        : "+f"(d[0]), "+f"(d[1]), "+f"(d[2]), "+f"(d[3])
        : "r"(a0), "r"(a1), "r"(a2), "r"(a3), "r"(b0), "r"(b1));
}

// ============================================================
// Kernel 1: per-node hc = [h, sqh], then A = hc@We0[8:200], B = hc@We0[200:392]
// ============================================================
__global__ void __launch_bounds__(256) node_pre_kernel(
    const float* __restrict__ x, const float* __restrict__ h,
    const float* __restrict__ We0)
{
    __shared__ float hc[192];
    __shared__ float sx[24];
    int n = blockIdx.x;
    int tid = threadIdx.x;
    if (tid < 24)  sx[tid] = x[n * 24 + tid];
    if (tid < 128) hc[tid] = h[n * 128 + tid];
    __syncthreads();
    if (tid < 64) {
        int h1 = tid >> 3, h2 = tid & 7;
        float s = 0.f;
        #pragma unroll
        for (int d = 0; d < 3; ++d) {
            float dx = sx[h1 * 3 + d] - sx[h2 * 3 + d];
            s += dx * dx;
        }
        hc[128 + tid] = s;
    }
    __syncthreads();
    float a = 0.f, b = 0.f;
    for (int k = 0; k < 192; ++k) {
        float v = hc[k];
        a = fmaf(v, We0[(8 + k) * 256 + tid], a);
        b = fmaf(v, We0[(200 + k) * 256 + tid], b);
    }
    g_A[n * 256 + tid] = a;
    g_B[n * 256 + tid] = b;
}

// ============================================================
// HMMA GEMM helper: acc = sIn[128 x 256] @ Wg[256 x 256] (tf32), 16 warps.
// Warp w: rows [(w>>3)*64, +64), cols [(w&7)*32, +32). 4 mt x 4 nt tiles.
// Weight staging is software-pipelined: next stage prefetched into regs
// (LDG.128) while current stage's MMAs run.
// ============================================================
__device__ __forceinline__ void gemm128x256_hmma(
    const float* __restrict__ Wg, const float* sIn, float* sW,
    float acc[4][4][4], int tid)
{
    const int w = tid >> 5;
    const int lane = tid & 31;
    const int g = lane >> 2, tg = lane & 3;
    const int n0 = (w & 7) * 32;
    const int m0 = (w >> 3) * 64;
    const int srow = tid >> 4;            // staging row 0..31
    const int scol4 = tid & 15;           // staging float4 group

    #pragma unroll
    for (int mt = 0; mt < 4; ++mt)
        #pragma unroll
        for (int nt = 0; nt < 4; ++nt)
            #pragma unroll
            for (int c = 0; c < 4; ++c) acc[mt][nt][c] = 0.f;

    const float4* Wg4 = (const float4*)Wg;   // 64 float4 per 256-col row
    float4 pre[4];
    #pragma unroll
    for (int j = 0; j < 4; ++j)
        pre[j] = Wg4[srow * 64 + scol4 + j * 16];

    for (int kb = 0; kb < 256; kb += KSTAGE) {
        __syncthreads();
        #pragma unroll
        for (int j = 0; j < 4; ++j) {
            float4 v = pre[j];
            float4 o;
            o.x = tf32r(v.x); o.y = tf32r(v.y); o.z = tf32r(v.z); o.w = tf32r(v.w);
            *(float4*)(sW + srow * SWPAD + (scol4 + j * 16) * 4) = o;
        }
        __syncthreads();
        if (kb + KSTAGE < 256) {
            #pragma unroll
            for (int j = 0; j < 4; ++j)
                pre[j] = Wg4[(kb + KSTAGE + srow) * 64 + scol4 + j * 16];
        }

        #pragma unroll
        for (int kc = 0; kc < KSTAGE / 8; ++kc) {
            const int k0 = kc * 8;
            uint32_t a[4][4], b[4][2];
            #pragma unroll
            for (int mt = 0; mt < 4; ++mt) {
                const float* base = sIn + (m0 + mt * 16 + g) * SAPAD + kb + k0 + tg;
                a[mt][0] = __float_as_uint(base[0]);
                a[mt][1] = __float_as_uint(base[8 * SAPAD]);
                a[mt][2] = __float_as_uint(base[4]);
                a[mt][3] = __float_as_uint(base[8 * SAPAD + 4]);
            }
            #pragma unroll
            for (int nt = 0; nt < 4; ++nt) {
                const float* bb = sW + (k0 + tg) * SWPAD + n0 + nt * 8 + g;
                b[nt][0] = __float_as_uint(bb[0]);
                b[nt][1] = __float_as_uint(bb[4 * SWPAD]);
            }
            #pragma unroll
            for (int mt = 0; mt < 4; ++mt)
                #pragma unroll
                for (int nt = 0; nt < 4; ++nt)
                    mma_tf32(acc[mt][nt], a[mt][0], a[mt][1], a[mt][2], a[mt][3],
                             b[nt][0], b[nt][1]);
        }
    }
    __syncthreads();
}

// ============================================================
// Kernel 2: fused edge pipeline
// grid (NN/TI, JS), 512 threads
// ============================================================
__global__ void __launch_bounds__(NTHREADS, 1) edge_kernel(
    const float* __restrict__ x,
    const float* __restrict__ We0, const float* __restrict__ be0,
    const float* __restrict__ We1, const float* __restrict__ be1,
    const float* __restrict__ Winf, const float* __restrict__ binf,
    const float* __restrict__ Wx0, const float* __restrict__ bx0,
    const float* __restrict__ Wx1, const float* __restrict__ bx1,
    const float* __restrict__ Wxo, const float* __restrict__ bxo)
{
    extern __shared__ float sm[];
    float* sA    = sm;                      // 128*260  (sAT aliases this)
    float* sAT   = sA;                      // 256*130 transposed b2 (alias)
    float* sW    = sA + EG * SAPAD;         // 32*264
    float* sW0s  = sW + KSTAGE * SWPAD;     // 8*256  (We0 rows 0..7)
    float* sWxo  = sW0s + 8 * MDIM;         // 256*8
    float* sWinf = sWxo + MDIM * 8;         // 256
    float* sBe0  = sWinf + MDIM;            // 256
    float* sBe1  = sBe0 + MDIM;             // 256
    float* sBx0  = sBe1 + MDIM;             // 256
    float* sBx1  = sBx0 + MDIM;             // 256
    float* sBxo  = sBx1 + MDIM;             // 8
    float* sMi   = sBxo + 8;                // 8*256
    float* sSqn  = sMi + TI * MDIM;         // 128*8
    float* sXi   = sSqn + EG * NH;          // 192
    float* sXj   = sXi + TI * 24;           // 384
    float* sE    = sXj + 384;               // 128
    float* sPx   = sE + EG;                 // 128*8
    float* sShift = sPx + EG * NH;          // 192

    int tid = threadIdx.x;
    int i0 = blockIdx.x * TI;
    int js = blockIdx.y;
    const int wlane = tid & 31;
    const int wg = wlane >> 2, wtg = wlane & 3;
    const int wn0 = ((tid >> 5) & 7) * 32;
    const int wm0 = (tid >> 8) * 64;

    // ---- stage constants ----
    for (int t = tid; t < 8 * MDIM; t += NTHREADS) sW0s[t] = We0[t];
    for (int t = tid; t < MDIM * 8; t += NTHREADS) sWxo[t] = Wxo[t];
    if (tid < 256) {
        sWinf[tid] = Winf[tid];
        sBe0[tid] = be0[tid];
        sBe1[tid] = be1[tid];
        sBx0[tid] = bx0[tid];
        sBx1[tid] = bx1[tid];
    }
    if (tid < 8) sBxo[tid] = bxo[tid];
    for (int t = tid; t < TI * MDIM; t += NTHREADS) sMi[t] = 0.f;
    if (tid < TI * 24) { sShift[tid] = 0.f; sXi[tid] = x[i0 * 24 + tid]; }
    float binf_v = binf[0];

    const int NJT = (NN / JS) / TJ;   // 8
    for (int jt = 0; jt < NJT; ++jt) {
        int j0 = js * (NN / JS) + jt * TJ;
        __syncthreads();   // protect sXj/sSqn from prior iteration's readers
        if (tid < TJ * 24) sXj[tid] = x[j0 * 24 + tid];
        __syncthreads();

        // ---- sqn tile (128 edges x 8 heads) ----
        for (int q = tid; q < EG * NH; q += NTHREADS) {
            int e = q >> 3, hh = q & 7;
            int ti = e >> 4, tj = e & 15;
            float s = 0.f;
            #pragma unroll
            for (int d = 0; d < 3; ++d) {
                float dx = sXj[tj * 24 + hh * 3 + d] - sXi[ti * 24 + hh * 3 + d];
                s += dx * dx;
            }
            sSqn[q] = s;
        }
        __syncthreads();

        // ---- layer 1 rank-combine: a1 = silu(A[j] + B[i] + be0 + sqn@We0[0:8]) ----
        // thread: col = tid&255, edge-half = tid>>8 (64 edges each)
        {
            int t = tid & 255, half = tid >> 8;
            float bvals[4], avals[TJ];
            #pragma unroll
            for (int ti = 0; ti < 4; ++ti)
                bvals[ti] = g_B[(i0 + half * 4 + ti) * MDIM + t] + sBe0[t];
            #pragma unroll
            for (int tj = 0; tj < TJ; ++tj) avals[tj] = g_A[(j0 + tj) * MDIM + t];
            #pragma unroll
            for (int e2 = 0; e2 < 64; ++e2) {
                int e = half * 64 + e2;
                int ti = e2 >> 4, tj = e2 & 15;
                float v = avals[tj] + bvals[ti];
                #pragma unroll
                for (int hh = 0; hh < 8; ++hh)
                    v = fmaf(sSqn[e * 8 + hh], sW0s[hh * MDIM + t], v);
                sA[e * SAPAD + t] = tf32r(siluf(v));
            }
        }
        __syncthreads();

        float acc[4][4][4];

        // ---- GEMM1 (HMMA tf32): m = silu(a1 @ We1 + be1) -> sA (rounded) ----
        gemm128x256_hmma(We1, sA, sW, acc, tid);
        #pragma unroll
        for (int mt = 0; mt < 4; ++mt)
            #pragma unroll
            for (int nt = 0; nt < 4; ++nt)
                #pragma unroll
                for (int c = 0; c < 4; ++c) {
                    int row = wm0 + mt * 16 + wg + ((c >= 2) ? 8 : 0);
                    int col = wn0 + nt * 8 + wtg * 2 + (c & 1);
                    sA[row * SAPAD + col] = tf32r(siluf(acc[mt][nt][c] + sBe1[col]));
                }
        __syncthreads();

        // ---- e gate: sigmoid(m . Winf + binf), zero diagonal ----
        {
            int e = tid >> 2, p = tid & 3;
            float s = 0.f;
            #pragma unroll 8
            for (int u = 0; u < 64; ++u) {
                int k = p + 4 * u;
                s = fmaf(sA[e * SAPAD + k], sWinf[k], s);
            }
            s += __shfl_xor_sync(0xffffffffu, s, 1);
            s += __shfl_xor_sync(0xffffffffu, s, 2);
            if (p == 0) {
                int gi = i0 + (e >> 4), gj = j0 + (e & 15);
                sE[e] = (gi == gj) ? 0.f : sigmf(s + binf_v);
            }
        }
        __syncthreads();

        // ---- m_i accumulation: thread owns (col = tid&255, edge-half tid>>8) ----
        {
            int t = tid & 255, half = tid >> 8;
            #pragma unroll 8
            for (int e2 = 0; e2 < 64; ++e2) {
                int e = half * 64 + e2;
                sMi[(e >> 4) * MDIM + t] = fmaf(sA[e * SAPAD + t], sE[e], sMi[(e >> 4) * MDIM + t]);
            }
        }
        __syncthreads();

        // ---- GEMM2 (HMMA tf32): b1 = silu(m @ Wx0 + bx0) -> sA (rounded) ----
        gemm128x256_hmma(Wx0, sA, sW, acc, tid);
        #pragma unroll
        for (int mt = 0; mt < 4; ++mt)
            #pragma unroll
            for (int nt = 0; nt < 4; ++nt)
                #pragma unroll
                for (int c = 0; c < 4; ++c) {
                    int row = wm0 + mt * 16 + wg + ((c >= 2) ? 8 : 0);
                    int col = wn0 + nt * 8 + wtg * 2 + (c & 1);
                    sA[row * SAPAD + col] = tf32r(siluf(acc[mt][nt][c] + sBx0[col]));
                }
        __syncthreads();

        // ---- GEMM3 (HMMA tf32): b2 = silu(b1 @ Wx1 + bx1) -> sAT (transposed; aliases sA) ----
        // Safe: helper's trailing __syncthreads guarantees all sA reads complete.
        gemm128x256_hmma(Wx1, sA, sW, acc, tid);
        #pragma unroll
        for (int mt = 0; mt < 4; ++mt)
            #pragma unroll
            for (int nt = 0; nt < 4; ++nt)
                #pragma unroll
                for (int c = 0; c < 4; ++c) {
                    int row = wm0 + mt * 16 + wg + ((c >= 2) ? 8 : 0);
                    int col = wn0 + nt * 8 + wtg * 2 + (c & 1);
                    sAT[col * SATPAD + row] = siluf(acc[mt][nt][c] + sBx1[col]);
                }
        __syncthreads();

        // ---- px = b2 @ Wxo + bxo (per-edge 8 heads), zero diagonal ----
        {
            int hh = tid >> 6, e0 = tid & 63;
            #pragma unroll
            for (int rep = 0; rep < 2; ++rep) {
                int e = e0 + rep * 64;
                float s = sBxo[hh];
                #pragma unroll 8
                for (int c = 0; c < MDIM; ++c)
                    s = fmaf(sAT[c * SATPAD + e], sWxo[c * 8 + hh], s);
                int gi = i0 + (e >> 4), gj = j0 + (e & 15);
                sPx[e * 8 + hh] = (gi == gj) ? 0.f : s;
            }
        }
        __syncthreads();

        // ---- shift accumulation ----
        if (tid < TI * 24) {
            int ti = tid / 24, r = tid % 24, hh = r / 3, d = r % 3;
            float a = 0.f;
            #pragma unroll
            for (int tj = 0; tj < TJ; ++tj) {
                int e = ti * 16 + tj;
                float sq = sSqn[e * 8 + hh];
                float nrm = sqrtf(sq + 1e-8f) + 1.0f;
                float dn = sXj[tj * 24 + hh * 3 + d] - sXi[ti * 24 + hh * 3 + d];
                a = fmaf(sPx[e * 8 + hh], dn / nrm, a);
            }
            sShift[tid] += a;
        }
    }
    __syncthreads();

    // ---- write partials ----
    for (int t = tid; t < TI * MDIM; t += NTHREADS) {
        int row = t >> 8, col = t & 255;
        g_mi_part[(js * NN + i0 + row) * MDIM + col] = sMi[t];
    }
    if (tid < TI * 24) {
        int ti = tid / 24, r = tid % 24;
        g_shift_part[(js * NN + i0 + ti) * 24 + r] = sShift[tid];
    }
}

// ============================================================
// Kernel 3: x_new = x + (sum_js shift_part) / (N-1)
// ============================================================
__global__ void finalize_x_kernel(const float* __restrict__ x, float* __restrict__ out)
{
    int idx = blockIdx.x * 256 + threadIdx.x;
    if (idx < NN * NH * 3) {
        float s = 0.f;
        #pragma unroll
        for (int js = 0; js < JS; ++js) s += g_shift_part[js * NN * 24 + idx];
        out[idx] = x[idx] + s * (1.0f / (float)(NN - 1));
    }
}

// ============================================================
// Kernel 4: phi_h  (8 nodes per block)
// ============================================================
#define NPB 8
__global__ void __launch_bounds__(256) h_kernel(
    const float* __restrict__ h,
    const float* __restrict__ Wh0, const float* __restrict__ bh0,
    const float* __restrict__ Wh1, const float* __restrict__ bh1,
    const float* __restrict__ Who, const float* __restrict__ bho,
    float* __restrict__ out)
{
    __shared__ float sin_s[NPB][384];
    __shared__ float s1[NPB][256];
    __shared__ float s2[NPB][256];
    int tid = threadIdx.x;
    int nb = blockIdx.x * NPB;

    for (int t = tid; t < NPB * 256; t += 256) {
        int nn = t >> 8, c = t & 255;
        float mi = 0.f;
        #pragma unroll
        for (int js = 0; js < JS; ++js)
            mi += g_mi_part[(js * NN + nb + nn) * MDIM + c];
        sin_s[nn][c] = mi;
    }
    for (int t = tid; t < NPB * 128; t += 256) {
        int nn = t >> 7, c = t & 127;
        sin_s[nn][256 + c] = h[(nb + nn) * 128 + c];
    }
    __syncthreads();
    {
        float acc[NPB];
        #pragma unroll
        for (int nn = 0; nn < NPB; ++nn) acc[nn] = 0.f;
        for (int k = 0; k < 384; ++k) {
            float w = Wh0[k * 256 + tid];
            #pragma unroll
            for (int nn = 0; nn < NPB; ++nn) acc[nn] = fmaf(sin_s[nn][k], w, acc[nn]);
        }
        float b = bh0[tid];
        #pragma unroll
        for (int nn = 0; nn < NPB; ++nn) s1[nn][tid] = siluf(acc[nn] + b);
    }
    __syncthreads();
    {
        float acc[NPB];
        #pragma unroll
        for (int nn = 0; nn < NPB; ++nn) acc[nn] = 0.f;
        for (int k = 0; k < 256; ++k) {
            float w = Wh1[k * 256 + tid];
            #pragma unroll
            for (int nn = 0; nn < NPB; ++nn) acc[nn] = fmaf(s1[nn][k], w, acc[nn]);
        }
        float b = bh1[tid];
        #pragma unroll
        for (int nn = 0; nn < NPB; ++nn) s2[nn][tid] = siluf(acc[nn] + b);
    }
    __syncthreads();
    if (tid < 128) {
        float acc[NPB];
        #pragma unroll
        for (int nn = 0; nn < NPB; ++nn) acc[nn] = 0.f;
        for (int k = 0; k < 256; ++k) {
            float w = Who[k * 128 + tid];
            #pragma unroll
            for (int nn = 0; nn < NPB; ++nn) acc[nn] = fmaf(s2[nn][k], w, acc[nn]);
        }
        float b = bho[tid];
        #pragma unroll
        for (int nn = 0; nn < NPB; ++nn)
            out[NN * NH * 3 + (nb + nn) * 128 + tid] = h[(nb + nn) * 128 + tid] + acc[nn] + b;
    }
}

// ============================================================
extern "C" void kernel_launch(void* const* d_in, const int* in_sizes, int n_in,
                              void* d_out, int out_size)
{
    const float* x    = (const float*)d_in[0];
    const float* h    = (const float*)d_in[1];
    const float* We0  = (const float*)d_in[2];
    const float* be0  = (const float*)d_in[3];
    const float* We1  = (const float*)d_in[4];
    const float* be1  = (const float*)d_in[5];
    const float* Winf = (const float*)d_in[6];
    const float* binf = (const float*)d_in[7];
    const float* Wx0  = (const float*)d_in[8];
    const float* bx0  = (const float*)d_in[9];
    const float* Wx1  = (const float*)d_in[10];
    const float* bx1  = (const float*)d_in[11];
    const float* Wxo  = (const float*)d_in[12];
    const float* bxo  = (const float*)d_in[13];
    const float* Wh0  = (const float*)d_in[14];
    const float* bh0  = (const float*)d_in[15];
    const float* Wh1  = (const float*)d_in[16];
    const float* bh1  = (const float*)d_in[17];
    const float* Who  = (const float*)d_in[18];
    const float* bho  = (const float*)d_in[19];
    float* out = (float*)d_out;

    node_pre_kernel<<<NN, 256>>>(x, h, We0);

    const int smem_floats =
        EG * SAPAD + KSTAGE * SWPAD + 8 * MDIM + MDIM * 8 +
        MDIM * 5 + 8 + TI * MDIM + EG * NH + TI * 24 + 384 + EG + EG * NH + TI * 24;
    const int smem_bytes = smem_floats * 4;
    static int attr_set = 0;
    if (!attr_set) {
        cudaFuncSetAttribute(edge_kernel, cudaFuncAttributeMaxDynamicSharedMemorySize, smem_bytes);
        attr_set = 1;
    }
    edge_kernel<<<dim3(NN / TI, JS), NTHREADS, smem_bytes>>>(
        x, We0, be0, We1, be1, Winf, binf, Wx0, bx0, Wx1, bx1, Wxo, bxo);

    finalize_x_kernel<<<(NN * NH * 3 + 255) / 256, 256>>>(x, out);

    h_kernel<<<NN / NPB, 256>>>(h, Wh0, bh0, Wh1, bh1, Who, bho, out);
}

// round 9
// speedup vs baseline: 1.1172x; 1.1172x over previous
#include <cuda_runtime.h>
#include <cstdint>

#define NN   512
#define HDIM 128
#define NH   8
#define MDIM 256
#define TI   4
#define TJ   16
#define EG   64      // edges per tile = TI*TJ
#define JS   4       // j splits
#define NTHREADS 256
#define SAPAD 260    // padded row stride for sA (conflict-free HMMA A loads)
#define SWPAD 264    // padded row stride for sW (conflict-free HMMA B loads)
#define KSTAGE 32    // weight rows staged per sync

// ---- scratch (device globals; no allocation allowed) ----
__device__ float g_A[NN * MDIM];                 // hc @ We0[8:200]
__device__ float g_B[NN * MDIM];                 // hc @ We0[200:392]
__device__ float g_mi_part[JS * NN * MDIM];     // partial m_i per j-split
__device__ float g_shift_part[JS * NN * NH * 3];

__device__ __forceinline__ float siluf(float v) { return v / (1.0f + __expf(-v)); }
__device__ __forceinline__ float sigmf(float v) { return 1.0f / (1.0f + __expf(-v)); }

__device__ __forceinline__ uint32_t f2tf32(float v) {
    uint32_t r;
    asm("cvt.rna.tf32.f32 %0, %1;" : "=r"(r) : "f"(v));
    return r;
}
__device__ __forceinline__ float tf32r(float v) { return __uint_as_float(f2tf32(v)); }

__device__ __forceinline__ void mma_tf32(float* d,
    uint32_t a0, uint32_t a1, uint32_t a2, uint32_t a3,
    uint32_t b0, uint32_t b1)
{
    asm volatile(
        "mma.sync.aligned.m16n8k8.row.col.f32.tf32.tf32.f32 "
        "{%0,%1,%2,%3}, {%4,%5,%6,%7}, {%8,%9}, {%0,%1,%2,%3};\n"
        : "+f"(d[0]), "+f"(d[1]), "+f"(d[2]), "+f"(d[3])
        : "r"(a0), "r"(a1), "r"(a2), "r"(a3), "r"(b0), "r"(b1));
}

// ============================================================
// Kernel 1: per-node hc = [h, sqh], then A = hc@We0[8:200], B = hc@We0[200:392]
// ============================================================
__global__ void __launch_bounds__(256) node_pre_kernel(
    const float* __restrict__ x, const float* __restrict__ h,
    const float* __restrict__ We0)
{
    __shared__ float hc[192];
    __shared__ float sx[24];
    int n = blockIdx.x;
    int tid = threadIdx.x;
    if (tid < 24)  sx[tid] = x[n * 24 + tid];
    if (tid < 128) hc[tid] = h[n * 128 + tid];
    __syncthreads();
    if (tid < 64) {
        int h1 = tid >> 3, h2 = tid & 7;
        float s = 0.f;
        #pragma unroll
        for (int d = 0; d < 3; ++d) {
            float dx = sx[h1 * 3 + d] - sx[h2 * 3 + d];
            s += dx * dx;
        }
        hc[128 + tid] = s;
    }
    __syncthreads();
    float a = 0.f, b = 0.f;
    for (int k = 0; k < 192; ++k) {
        float v = hc[k];
        a = fmaf(v, We0[(8 + k) * 256 + tid], a);
        b = fmaf(v, We0[(200 + k) * 256 + tid], b);
    }
    g_A[n * 256 + tid] = a;
    g_B[n * 256 + tid] = b;
}

// ============================================================
// HMMA GEMM helper (software-pipelined weight staging, 8 warps):
// acc = sIn[64 x 256] @ Wg[256 x 256] (tf32). Warp w owns cols [32w,32w+32).
// Next 32-row weight stage is prefetched into registers (LDG.128) while the
// current stage's MMAs run, hiding L2 latency.
// ============================================================
__device__ __forceinline__ void gemm64x256_hmma(
    const float* __restrict__ Wg, const float* sIn, float* sW,
    float acc[4][4][4], int tid)
{
    const int w = tid >> 5;
    const int lane = tid & 31;
    const int g = lane >> 2, tg = lane & 3;
    const int n0 = w * 32;
    const int srow = tid >> 3;    // staging row 0..31
    const int scol4 = tid & 7;    // staging float4 base

    #pragma unroll
    for (int mt = 0; mt < 4; ++mt)
        #pragma unroll
        for (int nt = 0; nt < 4; ++nt)
            #pragma unroll
            for (int c = 0; c < 4; ++c) acc[mt][nt][c] = 0.f;

    const float4* Wg4 = (const float4*)Wg;   // 64 float4 per 256-col row
    float4 pre[8];
    #pragma unroll
    for (int j = 0; j < 8; ++j)
        pre[j] = Wg4[srow * 64 + scol4 + j * 8];

    for (int kb = 0; kb < 256; kb += KSTAGE) {
        __syncthreads();
        #pragma unroll
        for (int j = 0; j < 8; ++j) {
            float4 v = pre[j];
            float4 o;
            o.x = tf32r(v.x); o.y = tf32r(v.y); o.z = tf32r(v.z); o.w = tf32r(v.w);
            *(float4*)(sW + srow * SWPAD + (scol4 + j * 8) * 4) = o;
        }
        __syncthreads();
        if (kb + KSTAGE < 256) {
            #pragma unroll
            for (int j = 0; j < 8; ++j)
                pre[j] = Wg4[(kb + KSTAGE + srow) * 64 + scol4 + j * 8];
        }

        #pragma unroll
        for (int kc = 0; kc < KSTAGE / 8; ++kc) {
            const int k0 = kc * 8;
            uint32_t a[4][4], b[4][2];
            #pragma unroll
            for (int mt = 0; mt < 4; ++mt) {
                const float* base = sIn + (mt * 16 + g) * SAPAD + kb + k0 + tg;
                a[mt][0] = __float_as_uint(base[0]);
                a[mt][1] = __float_as_uint(base[8 * SAPAD]);
                a[mt][2] = __float_as_uint(base[4]);
                a[mt][3] = __float_as_uint(base[8 * SAPAD + 4]);
            }
            #pragma unroll
            for (int nt = 0; nt < 4; ++nt) {
                const float* bb = sW + (k0 + tg) * SWPAD + n0 + nt * 8 + g;
                b[nt][0] = __float_as_uint(bb[0]);
                b[nt][1] = __float_as_uint(bb[4 * SWPAD]);
            }
            #pragma unroll
            for (int mt = 0; mt < 4; ++mt)
                #pragma unroll
                for (int nt = 0; nt < 4; ++nt)
                    mma_tf32(acc[mt][nt], a[mt][0], a[mt][1], a[mt][2], a[mt][3],
                             b[nt][0], b[nt][1]);
        }
    }
    __syncthreads();
}

// ============================================================
// Kernel 2: fused edge pipeline
// grid (NN/TI, JS), 256 threads
// ============================================================
__global__ void __launch_bounds__(NTHREADS, 1) edge_kernel(
    const float* __restrict__ x,
    const float* __restrict__ We0, const float* __restrict__ be0,
    const float* __restrict__ We1, const float* __restrict__ be1,
    const float* __restrict__ Winf, const float* __restrict__ binf,
    const float* __restrict__ Wx0, const float* __restrict__ bx0,
    const float* __restrict__ Wx1, const float* __restrict__ bx1,
    const float* __restrict__ Wxo, const float* __restrict__ bxo)
{
    extern __shared__ float sm[];
    float* sA    = sm;                      // 64*260
    float* sW    = sA + EG * SAPAD;         // 32*264
    float* sW0s  = sW + KSTAGE * SWPAD;     // 8*256  (We0 rows 0..7)
    float* sWxo  = sW0s + 8 * MDIM;         // 256*8
    float* sWinf = sWxo + MDIM * 8;         // 256
    float* sBe0  = sWinf + MDIM;            // 256
    float* sBe1  = sBe0 + MDIM;             // 256
    float* sBx0  = sBe1 + MDIM;             // 256
    float* sBx1  = sBx0 + MDIM;             // 256
    float* sBxo  = sBx1 + MDIM;             // 8
    float* sMi   = sBxo + 8;                // 4*256
    float* sSqn  = sMi + TI * MDIM;         // 64*8
    float* sXi   = sSqn + EG * NH;          // 96
    float* sXj   = sXi + 96;                // 384
    float* sE    = sXj + 384;               // 64
    float* sPx   = sE + EG;                 // 64*8
    float* sShift = sPx + EG * NH;          // 96
    float* sEp   = sShift + 96;             // 8*64   per-warp e partials
    float* sPxW  = sEp + 8 * EG;            // 8*64*8 per-warp px partials

    int tid = threadIdx.x;
    int i0 = blockIdx.x * TI;
    int js = blockIdx.y;
    const int wid = tid >> 5;
    const int wlane = tid & 31;
    const int wg = wlane >> 2, wtg = wlane & 3;
    const int wn0 = wid * 32;

    // ---- stage constants ----
    for (int t = tid; t < 8 * MDIM; t += NTHREADS) sW0s[t] = We0[t];
    for (int t = tid; t < MDIM * 8; t += NTHREADS) sWxo[t] = Wxo[t];
    sWinf[tid] = Winf[tid];
    sBe0[tid] = be0[tid];
    sBe1[tid] = be1[tid];
    sBx0[tid] = bx0[tid];
    sBx1[tid] = bx1[tid];
    if (tid < 8) sBxo[tid] = bxo[tid];
    for (int t = tid; t < TI * MDIM; t += NTHREADS) sMi[t] = 0.f;
    if (tid < 96) { sShift[tid] = 0.f; sXi[tid] = x[i0 * 24 + tid]; }
    float binf_v = binf[0];

    const int NJT = (NN / JS) / TJ;   // 8
    for (int jt = 0; jt < NJT; ++jt) {
        int j0 = js * (NN / JS) + jt * TJ;
        __syncthreads();   // protect sXj/sSqn/sPx from prior iteration's readers
        for (int t = tid; t < TJ * 24; t += NTHREADS) sXj[t] = x[j0 * 24 + t];
        __syncthreads();

        // ---- sqn tile ----
        for (int q = tid; q < EG * NH; q += NTHREADS) {
            int e = q >> 3, hh = q & 7;
            int ti = e >> 4, tj = e & 15;
            float s = 0.f;
            #pragma unroll
            for (int d = 0; d < 3; ++d) {
                float dx = sXj[tj * 24 + hh * 3 + d] - sXi[ti * 24 + hh * 3 + d];
                s += dx * dx;
            }
            sSqn[q] = s;
        }
        __syncthreads();

        // ---- layer 1 rank-combine: a1 = silu(A[j] + B[i] + be0 + sqn@We0[0:8]) ----
        {
            int t = tid;
            float bvals[TI], avals[TJ];
            #pragma unroll
            for (int ti = 0; ti < TI; ++ti) bvals[ti] = g_B[(i0 + ti) * MDIM + t] + sBe0[t];
            #pragma unroll
            for (int tj = 0; tj < TJ; ++tj) avals[tj] = g_A[(j0 + tj) * MDIM + t];
            #pragma unroll
            for (int e = 0; e < EG; ++e) {
                int ti = e >> 4, tj = e & 15;
                float v = avals[tj] + bvals[ti];
                #pragma unroll
                for (int hh = 0; hh < 8; ++hh)
                    v = fmaf(sSqn[e * 8 + hh], sW0s[hh * MDIM + t], v);
                sA[e * SAPAD + t] = tf32r(siluf(v));
            }
        }
        __syncthreads();

        float acc[4][4][4];

        // ---- GEMM1: m = silu(a1 @ We1 + be1) -> sA; fold e-gate partials ----
        gemm64x256_hmma(We1, sA, sW, acc, tid);
        {
            float ep[4][2];
            #pragma unroll
            for (int mt = 0; mt < 4; ++mt) { ep[mt][0] = 0.f; ep[mt][1] = 0.f; }
            #pragma unroll
            for (int mt = 0; mt < 4; ++mt)
                #pragma unroll
                for (int nt = 0; nt < 4; ++nt)
                    #pragma unroll
                    for (int c = 0; c < 4; ++c) {
                        int hi = c >> 1;
                        int row = mt * 16 + wg + 8 * hi;
                        int col = wn0 + nt * 8 + wtg * 2 + (c & 1);
                        float v = siluf(acc[mt][nt][c] + sBe1[col]);
                        sA[row * SAPAD + col] = tf32r(v);
                        ep[mt][hi] = fmaf(v, sWinf[col], ep[mt][hi]);
                    }
            #pragma unroll
            for (int mt = 0; mt < 4; ++mt)
                #pragma unroll
                for (int hi = 0; hi < 2; ++hi) {
                    ep[mt][hi] += __shfl_xor_sync(0xffffffffu, ep[mt][hi], 1);
                    ep[mt][hi] += __shfl_xor_sync(0xffffffffu, ep[mt][hi], 2);
                }
            if (wtg == 0) {
                #pragma unroll
                for (int mt = 0; mt < 4; ++mt)
                    #pragma unroll
                    for (int hi = 0; hi < 2; ++hi)
                        sEp[wid * EG + mt * 16 + wg + 8 * hi] = ep[mt][hi];
            }
        }
        __syncthreads();

        // ---- e final: sum warp partials, sigmoid, zero diagonal ----
        if (tid < EG) {
            float s = 0.f;
            #pragma unroll
            for (int w = 0; w < 8; ++w) s += sEp[w * EG + tid];
            int gi = i0 + (tid >> 4), gj = j0 + (tid & 15);
            sE[tid] = (gi == gj) ? 0.f : sigmf(s + binf_v);
        }
        __syncthreads();

        // ---- m_i accumulation (thread owns column tid) ----
        {
            int t = tid;
            #pragma unroll 8
            for (int e = 0; e < EG; ++e)
                sMi[(e >> 4) * MDIM + t] = fmaf(sA[e * SAPAD + t], sE[e], sMi[(e >> 4) * MDIM + t]);
        }
        __syncthreads();

        // ---- GEMM2: b1 = silu(m @ Wx0 + bx0) -> sA (rounded) ----
        gemm64x256_hmma(Wx0, sA, sW, acc, tid);
        #pragma unroll
        for (int mt = 0; mt < 4; ++mt)
            #pragma unroll
            for (int nt = 0; nt < 4; ++nt)
                #pragma unroll
                for (int c = 0; c < 4; ++c) {
                    int row = mt * 16 + wg + ((c >= 2) ? 8 : 0);
                    int col = wn0 + nt * 8 + wtg * 2 + (c & 1);
                    sA[row * SAPAD + col] = tf32r(siluf(acc[mt][nt][c] + sBx0[col]));
                }
        __syncthreads();

        // ---- GEMM3: b2 = silu(b1 @ Wx1 + bx1), px folded in-register ----
        gemm64x256_hmma(Wx1, sA, sW, acc, tid);
        {
            // activate in place
            #pragma unroll
            for (int mt = 0; mt < 4; ++mt)
                #pragma unroll
                for (int nt = 0; nt < 4; ++nt)
                    #pragma unroll
                    for (int c = 0; c < 4; ++c) {
                        int col = wn0 + nt * 8 + wtg * 2 + (c & 1);
                        acc[mt][nt][c] = siluf(acc[mt][nt][c] + sBx1[col]);
                    }
            // px partials per head
            #pragma unroll
            for (int hh = 0; hh < 8; ++hh) {
                float pxp[4][2];
                #pragma unroll
                for (int mt = 0; mt < 4; ++mt) { pxp[mt][0] = 0.f; pxp[mt][1] = 0.f; }
                #pragma unroll
                for (int nt = 0; nt < 4; ++nt)
                    #pragma unroll
                    for (int lo = 0; lo < 2; ++lo) {
                        int col = wn0 + nt * 8 + wtg * 2 + lo;
                        float wv = sWxo[col * 8 + hh];
                        #pragma unroll
                        for (int mt = 0; mt < 4; ++mt) {
                            pxp[mt][0] = fmaf(acc[mt][nt][lo],     wv, pxp[mt][0]);
                            pxp[mt][1] = fmaf(acc[mt][nt][2 + lo], wv, pxp[mt][1]);
                        }
                    }
                #pragma unroll
                for (int mt = 0; mt < 4; ++mt)
                    #pragma unroll
                    for (int hi = 0; hi < 2; ++hi) {
                        pxp[mt][hi] += __shfl_xor_sync(0xffffffffu, pxp[mt][hi], 1);
                        pxp[mt][hi] += __shfl_xor_sync(0xffffffffu, pxp[mt][hi], 2);
                    }
                if (wtg == 0) {
                    #pragma unroll
                    for (int mt = 0; mt < 4; ++mt)
                        #pragma unroll
                        for (int hi = 0; hi < 2; ++hi)
                            sPxW[wid * (EG * NH) + (mt * 16 + wg + 8 * hi) * 8 + hh] = pxp[mt][hi];
                }
            }
        }
        __syncthreads();

        // ---- px final: sum warp partials + bias, zero diagonal ----
        #pragma unroll
        for (int rep = 0; rep < 2; ++rep) {
            int q = tid + rep * NTHREADS;
            int row = q >> 3, hh = q & 7;
            float s = sBxo[hh];
            #pragma unroll
            for (int w = 0; w < 8; ++w) s += sPxW[w * (EG * NH) + q];
            int gi = i0 + (row >> 4), gj = j0 + (row & 15);
            sPx[q] = (gi == gj) ? 0.f : s;
        }
        __syncthreads();

        // ---- shift accumulation ----
        if (tid < 96) {
            int ti = tid / 24, r = tid % 24, hh = r / 3, d = r % 3;
            float a = 0.f;
            #pragma unroll
            for (int tj = 0; tj < TJ; ++tj) {
                int e = ti * 16 + tj;
                float sq = sSqn[e * 8 + hh];
                float nrm = sqrtf(sq + 1e-8f) + 1.0f;
                float dn = sXj[tj * 24 + hh * 3 + d] - sXi[ti * 24 + hh * 3 + d];
                a = fmaf(sPx[e * 8 + hh], dn / nrm, a);
            }
            sShift[tid] += a;
        }
    }
    __syncthreads();

    // ---- write partials ----
    {
        int t = tid;
        #pragma unroll
        for (int ti = 0; ti < TI; ++ti)
            g_mi_part[(js * NN + i0 + ti) * MDIM + t] = sMi[ti * MDIM + t];
    }
    if (tid < 96) {
        int ti = tid / 24, r = tid % 24;
        g_shift_part[(js * NN + i0 + ti) * 24 + r] = sShift[tid];
    }
}

// ============================================================
// Kernel 3: x_new = x + (sum_js shift_part) / (N-1)
// ============================================================
__global__ void finalize_x_kernel(const float* __restrict__ x, float* __restrict__ out)
{
    int idx = blockIdx.x * 256 + threadIdx.x;
    if (idx < NN * NH * 3) {
        float s = 0.f;
        #pragma unroll
        for (int js = 0; js < JS; ++js) s += g_shift_part[js * NN * 24 + idx];
        out[idx] = x[idx] + s * (1.0f / (float)(NN - 1));
    }
}

// ============================================================
// Kernel 4: phi_h  (2 nodes per block for occupancy)
// ============================================================
#define NPB 2
__global__ void __launch_bounds__(256) h_kernel(
    const float* __restrict__ h,
    const float* __restrict__ Wh0, const float* __restrict__ bh0,
    const float* __restrict__ Wh1, const float* __restrict__ bh1,
    const float* __restrict__ Who, const float* __restrict__ bho,
    float* __restrict__ out)
{
    __shared__ float sin_s[NPB][384];
    __shared__ float s1[NPB][256];
    __shared__ float s2[NPB][256];
    int tid = threadIdx.x;
    int nb = blockIdx.x * NPB;

    for (int t = tid; t < NPB * 256; t += 256) {
        int nn = t >> 8, c = t & 255;
        float mi = 0.f;
        #pragma unroll
        for (int js = 0; js < JS; ++js)
            mi += g_mi_part[(js * NN + nb + nn) * MDIM + c];
        sin_s[nn][c] = mi;
    }
    for (int t = tid; t < NPB * 128; t += 256) {
        int nn = t >> 7, c = t & 127;
        sin_s[nn][256 + c] = h[(nb + nn) * 128 + c];
    }
    __syncthreads();
    {
        float acc[NPB];
        #pragma unroll
        for (int nn = 0; nn < NPB; ++nn) acc[nn] = 0.f;
        for (int k = 0; k < 384; ++k) {
            float w = Wh0[k * 256 + tid];
            #pragma unroll
            for (int nn = 0; nn < NPB; ++nn) acc[nn] = fmaf(sin_s[nn][k], w, acc[nn]);
        }
        float b = bh0[tid];
        #pragma unroll
        for (int nn = 0; nn < NPB; ++nn) s1[nn][tid] = siluf(acc[nn] + b);
    }
    __syncthreads();
    {
        float acc[NPB];
        #pragma unroll
        for (int nn = 0; nn < NPB; ++nn) acc[nn] = 0.f;
        for (int k = 0; k < 256; ++k) {
            float w = Wh1[k * 256 + tid];
            #pragma unroll
            for (int nn = 0; nn < NPB; ++nn) acc[nn] = fmaf(s1[nn][k], w, acc[nn]);
        }
        float b = bh1[tid];
        #pragma unroll
        for (int nn = 0; nn < NPB; ++nn) s2[nn][tid] = siluf(acc[nn] + b);
    }
    __syncthreads();
    if (tid < 128) {
        float acc[NPB];
        #pragma unroll
        for (int nn = 0; nn < NPB; ++nn) acc[nn] = 0.f;
        for (int k = 0; k < 256; ++k) {
            float w = Who[k * 128 + tid];
            #pragma unroll
            for (int nn = 0; nn < NPB; ++nn) acc[nn] = fmaf(s2[nn][k], w, acc[nn]);
        }
        float b = bho[tid];
        #pragma unroll
        for (int nn = 0; nn < NPB; ++nn)
            out[NN * NH * 3 + (nb + nn) * 128 + tid] = h[(nb + nn) * 128 + tid] + acc[nn] + b;
    }
}

// ============================================================
extern "C" void kernel_launch(void* const* d_in, const int* in_sizes, int n_in,
                              void* d_out, int out_size)
{
    const float* x    = (const float*)d_in[0];
    const float* h    = (const float*)d_in[1];
    const float* We0  = (const float*)d_in[2];
    const float* be0  = (const float*)d_in[3];
    const float* We1  = (const float*)d_in[4];
    const float* be1  = (const float*)d_in[5];
    const float* Winf = (const float*)d_in[6];
    const float* binf = (const float*)d_in[7];
    const float* Wx0  = (const float*)d_in[8];
    const float* bx0  = (const float*)d_in[9];
    const float* Wx1  = (const float*)d_in[10];
    const float* bx1  = (const float*)d_in[11];
    const float* Wxo  = (const float*)d_in[12];
    const float* bxo  = (const float*)d_in[13];
    const float* Wh0  = (const float*)d_in[14];
    const float* bh0  = (const float*)d_in[15];
    const float* Wh1  = (const float*)d_in[16];
    const float* bh1  = (const float*)d_in[17];
    const float* Who  = (const float*)d_in[18];
    const float* bho  = (const float*)d_in[19];
    float* out = (float*)d_out;

    node_pre_kernel<<<NN, 256>>>(x, h, We0);

    const int smem_floats =
        EG * SAPAD + KSTAGE * SWPAD + 8 * MDIM + MDIM * 8 +
        MDIM * 5 + 8 + TI * MDIM + EG * NH + 96 + 384 + EG + EG * NH + 96 +
        8 * EG + 8 * EG * NH;
    const int smem_bytes = smem_floats * 4;
    static int attr_set = 0;
    if (!attr_set) {
        cudaFuncSetAttribute(edge_kernel, cudaFuncAttributeMaxDynamicSharedMemorySize, smem_bytes);
        attr_set = 1;
    }
    edge_kernel<<<dim3(NN / TI, JS), NTHREADS, smem_bytes>>>(
        x, We0, be0, We1, be1, Winf, binf, Wx0, bx0, Wx1, bx1, Wxo, bxo);

    finalize_x_kernel<<<(NN * NH * 3 + 255) / 256, 256>>>(x, out);

    h_kernel<<<NN / NPB, 256>>>(h, Wh0, bh0, Wh1, bh1, Who, bho, out);
}

// round 12
// speedup vs baseline: 1.1276x; 1.0093x over previous
#include <cuda_runtime.h>
#include <cstdint>

#define NN   512
#define HDIM 128
#define NH   8
#define MDIM 256
#define TI   4
#define TJ   16
#define EG   64      // edges per tile = TI*TJ
#define JS   4       // j splits
#define NTHREADS 256
#define SAPAD 260    // padded row stride for sA (conflict-free HMMA A loads)
#define SWPAD 264    // padded row stride for sW (conflict-free HMMA B loads)
#define KSTAGE 16    // weight rows staged per sync (halved: fits 2 CTAs/SM + reg budget)
#define UNION_FLOATS 4736   // staging buffer (16*264=4224) ∪ sPxW(4096) ∪ sEp@4224(512)

// ---- scratch (device globals; no allocation allowed) ----
__device__ float g_A[NN * MDIM];                 // hc @ We0[8:200]
__device__ float g_B[NN * MDIM];                 // hc @ We0[200:392]
__device__ float g_mi_part[JS * NN * MDIM];     // partial m_i per j-split
__device__ float g_shift_part[JS * NN * NH * 3];

__device__ __forceinline__ float siluf(float v) {
    return __fdividef(v, 1.0f + __expf(-v));
}
__device__ __forceinline__ float sigmf(float v) {
    return __fdividef(1.0f, 1.0f + __expf(-v));
}

__device__ __forceinline__ uint32_t f2tf32(float v) {
    uint32_t r;
    asm("cvt.rna.tf32.f32 %0, %1;" : "=r"(r) : "f"(v));
    return r;
}
__device__ __forceinline__ float tf32r(float v) { return __uint_as_float(f2tf32(v)); }

__device__ __forceinline__ void mma_tf32(float* d,
    uint32_t a0, uint32_t a1, uint32_t a2, uint32_t a3,
    uint32_t b0, uint32_t b1)
{
    asm volatile(
        "mma.sync.aligned.m16n8k8.row.col.f32.tf32.tf32.f32 "
        "{%0,%1,%2,%3}, {%4,%5,%6,%7}, {%8,%9}, {%0,%1,%2,%3};\n"
        : "+f"(d[0]), "+f"(d[1]), "+f"(d[2]), "+f"(d[3])
        : "r"(a0), "r"(a1), "r"(a2), "r"(a3), "r"(b0), "r"(b1));
}

// ============================================================
// Kernel 1: per-node hc = [h, sqh], then A = hc@We0[8:200], B = hc@We0[200:392]
// ============================================================
__global__ void __launch_bounds__(256) node_pre_kernel(
    const float* __restrict__ x, const float* __restrict__ h,
    const float* __restrict__ We0)
{
    __shared__ float hc[192];
    __shared__ float sx[24];
    int n = blockIdx.x;
    int tid = threadIdx.x;
    if (tid < 24)  sx[tid] = x[n * 24 + tid];
    if (tid < 128) hc[tid] = h[n * 128 + tid];
    __syncthreads();
    if (tid < 64) {
        int h1 = tid >> 3, h2 = tid & 7;
        float s = 0.f;
        #pragma unroll
        for (int d = 0; d < 3; ++d) {
            float dx = sx[h1 * 3 + d] - sx[h2 * 3 + d];
            s += dx * dx;
        }
        hc[128 + tid] = s;
    }
    __syncthreads();
    float a = 0.f, b = 0.f;
    for (int k = 0; k < 192; ++k) {
        float v = hc[k];
        a = fmaf(v, We0[(8 + k) * 256 + tid], a);
        b = fmaf(v, We0[(200 + k) * 256 + tid], b);
    }
    g_A[n * 256 + tid] = a;
    g_B[n * 256 + tid] = b;
}

// ============================================================
// HMMA GEMM helper (software-pipelined weight staging, 8 warps):
// acc = sIn[64 x 256] @ Wg[256 x 256] (tf32). Warp w owns cols [32w,32w+32).
// Next 16-row weight stage prefetched into registers (4x LDG.128/thread)
// while the current stage's MMAs run.
// ============================================================
__device__ __forceinline__ void gemm64x256_hmma(
    const float* __restrict__ Wg, const float* sIn, float* sW,
    float acc[4][4][4], int tid)
{
    const int w = tid >> 5;
    const int lane = tid & 31;
    const int g = lane >> 2, tg = lane & 3;
    const int n0 = w * 32;
    const int srow = tid >> 4;    // staging row 0..15
    const int scol4 = tid & 15;   // staging float4 base

    #pragma unroll
    for (int mt = 0; mt < 4; ++mt)
        #pragma unroll
        for (int nt = 0; nt < 4; ++nt)
            #pragma unroll
            for (int c = 0; c < 4; ++c) acc[mt][nt][c] = 0.f;

    const float4* Wg4 = (const float4*)Wg;   // 64 float4 per 256-col row
    float4 pre[4];
    #pragma unroll
    for (int j = 0; j < 4; ++j)
        pre[j] = Wg4[srow * 64 + scol4 + j * 16];

    for (int kb = 0; kb < 256; kb += KSTAGE) {
        __syncthreads();
        #pragma unroll
        for (int j = 0; j < 4; ++j) {
            float4 v = pre[j];
            float4 o;
            o.x = tf32r(v.x); o.y = tf32r(v.y); o.z = tf32r(v.z); o.w = tf32r(v.w);
            *(float4*)(sW + srow * SWPAD + (scol4 + j * 16) * 4) = o;
        }
        __syncthreads();
        if (kb + KSTAGE < 256) {
            #pragma unroll
            for (int j = 0; j < 4; ++j)
                pre[j] = Wg4[(kb + KSTAGE + srow) * 64 + scol4 + j * 16];
        }

        #pragma unroll
        for (int kc = 0; kc < KSTAGE / 8; ++kc) {
            const int k0 = kc * 8;
            uint32_t a[4][4], b[4][2];
            #pragma unroll
            for (int mt = 0; mt < 4; ++mt) {
                const float* base = sIn + (mt * 16 + g) * SAPAD + kb + k0 + tg;
                a[mt][0] = __float_as_uint(base[0]);
                a[mt][1] = __float_as_uint(base[8 * SAPAD]);
                a[mt][2] = __float_as_uint(base[4]);
                a[mt][3] = __float_as_uint(base[8 * SAPAD + 4]);
            }
            #pragma unroll
            for (int nt = 0; nt < 4; ++nt) {
                const float* bb = sW + (k0 + tg) * SWPAD + n0 + nt * 8 + g;
                b[nt][0] = __float_as_uint(bb[0]);
                b[nt][1] = __float_as_uint(bb[4 * SWPAD]);
            }
            #pragma unroll
            for (int mt = 0; mt < 4; ++mt)
                #pragma unroll
                for (int nt = 0; nt < 4; ++nt)
                    mma_tf32(acc[mt][nt], a[mt][0], a[mt][1], a[mt][2], a[mt][3],
                             b[nt][0], b[nt][1]);
        }
    }
    __syncthreads();
}

// ============================================================
// Kernel 2: fused edge pipeline
// grid (NN/TI, JS), 256 threads, 2 CTAs/SM
// ============================================================
__global__ void __launch_bounds__(NTHREADS, 2) edge_kernel(
    const float* __restrict__ x,
    const float* __restrict__ We0, const float* __restrict__ be0,
    const float* __restrict__ We1, const float* __restrict__ be1,
    const float* __restrict__ Winf, const float* __restrict__ binf,
    const float* __restrict__ Wx0, const float* __restrict__ bx0,
    const float* __restrict__ Wx1, const float* __restrict__ bx1,
    const float* __restrict__ Wxo, const float* __restrict__ bxo)
{
    extern __shared__ float sm[];
    float* sA    = sm;                      // 64*260
    float* sU    = sA + EG * SAPAD;         // UNION: staging(16*264=4224) / sPxW(4096) / sEp@4224(512)
    float* sW    = sU;                      // staging buffer (GEMM phases)
    float* sPxW  = sU;                      // per-warp px partials (epi3 phase)
    float* sEp   = sU + 4224;               // per-warp e partials (epi1 phase)
    float* sWxo  = sU + UNION_FLOATS;       // 256*8
    float* sWinf = sWxo + MDIM * 8;         // 256
    float* sBe0  = sWinf + MDIM;            // 256
    float* sBe1  = sBe0 + MDIM;             // 256
    float* sBx0  = sBe1 + MDIM;             // 256
    float* sBx1  = sBx0 + MDIM;             // 256
    float* sBxo  = sBx1 + MDIM;             // 8
    float* sMi   = sBxo + 8;                // 4*256
    float* sSqn  = sMi + TI * MDIM;         // 64*8
    float* sXi   = sSqn + EG * NH;          // 96
    float* sXj   = sXi + 96;                // 384
    float* sE    = sXj + 384;               // 64
    float* sPx   = sE + EG;                 // 64*8
    float* sShift = sPx + EG * NH;          // 96

    int tid = threadIdx.x;
    int i0 = blockIdx.x * TI;
    int js = blockIdx.y;
    const int wid = tid >> 5;
    const int wlane = tid & 31;
    const int wg = wlane >> 2, wtg = wlane & 3;
    const int wn0 = wid * 32;

    // ---- stage constants ----
    // We0 rows 0..7: each thread only ever needs column `tid` -> registers.
    float w0s[8];
    #pragma unroll
    for (int hh = 0; hh < 8; ++hh) w0s[hh] = We0[hh * MDIM + tid];
    for (int t = tid; t < MDIM * 8; t += NTHREADS) sWxo[t] = Wxo[t];
    sWinf[tid] = Winf[tid];
    sBe0[tid] = be0[tid];
    sBe1[tid] = be1[tid];
    sBx0[tid] = bx0[tid];
    sBx1[tid] = bx1[tid];
    if (tid < 8) sBxo[tid] = bxo[tid];
    for (int t = tid; t < TI * MDIM; t += NTHREADS) sMi[t] = 0.f;
    if (tid < 96) { sShift[tid] = 0.f; sXi[tid] = x[i0 * 24 + tid]; }
    float binf_v = binf[0];

    const int NJT = (NN / JS) / TJ;   // 8
    for (int jt = 0; jt < NJT; ++jt) {
        int j0 = js * (NN / JS) + jt * TJ;
        __syncthreads();   // protect sXj/sSqn/sPx from prior iteration's readers
        for (int t = tid; t < TJ * 24; t += NTHREADS) sXj[t] = x[j0 * 24 + t];
        __syncthreads();

        // ---- sqn tile ----
        for (int q = tid; q < EG * NH; q += NTHREADS) {
            int e = q >> 3, hh = q & 7;
            int ti = e >> 4, tj = e & 15;
            float s = 0.f;
            #pragma unroll
            for (int d = 0; d < 3; ++d) {
                float dx = sXj[tj * 24 + hh * 3 + d] - sXi[ti * 24 + hh * 3 + d];
                s += dx * dx;
            }
            sSqn[q] = s;
        }
        __syncthreads();

        // ---- layer 1 rank-combine: a1 = silu(A[j] + B[i] + be0 + sqn@We0[0:8]) ----
        {
            int t = tid;
            float bvals[TI], avals[TJ];
            #pragma unroll
            for (int ti = 0; ti < TI; ++ti) bvals[ti] = g_B[(i0 + ti) * MDIM + t] + sBe0[t];
            #pragma unroll
            for (int tj = 0; tj < TJ; ++tj) avals[tj] = g_A[(j0 + tj) * MDIM + t];
            #pragma unroll
            for (int e = 0; e < EG; ++e) {
                int ti = e >> 4, tj = e & 15;
                float v = avals[tj] + bvals[ti];
                #pragma unroll
                for (int hh = 0; hh < 8; ++hh)
                    v = fmaf(sSqn[e * 8 + hh], w0s[hh], v);
                sA[e * SAPAD + t] = tf32r(siluf(v));
            }
        }
        __syncthreads();

        float acc[4][4][4];

        // ---- GEMM1: m = silu(a1 @ We1 + be1) -> sA; fold e-gate partials ----
        gemm64x256_hmma(We1, sA, sW, acc, tid);
        {
            float ep[4][2];
            #pragma unroll
            for (int mt = 0; mt < 4; ++mt) { ep[mt][0] = 0.f; ep[mt][1] = 0.f; }
            #pragma unroll
            for (int mt = 0; mt < 4; ++mt)
                #pragma unroll
                for (int nt = 0; nt < 4; ++nt)
                    #pragma unroll
                    for (int c = 0; c < 4; ++c) {
                        int hi = c >> 1;
                        int row = mt * 16 + wg + 8 * hi;
                        int col = wn0 + nt * 8 + wtg * 2 + (c & 1);
                        float v = siluf(acc[mt][nt][c] + sBe1[col]);
                        sA[row * SAPAD + col] = tf32r(v);
                        ep[mt][hi] = fmaf(v, sWinf[col], ep[mt][hi]);
                    }
            #pragma unroll
            for (int mt = 0; mt < 4; ++mt)
                #pragma unroll
                for (int hi = 0; hi < 2; ++hi) {
                    ep[mt][hi] += __shfl_xor_sync(0xffffffffu, ep[mt][hi], 1);
                    ep[mt][hi] += __shfl_xor_sync(0xffffffffu, ep[mt][hi], 2);
                }
            if (wtg == 0) {
                #pragma unroll
                for (int mt = 0; mt < 4; ++mt)
                    #pragma unroll
                    for (int hi = 0; hi < 2; ++hi)
                        sEp[wid * EG + mt * 16 + wg + 8 * hi] = ep[mt][hi];
            }
        }
        __syncthreads();

        // ---- e final: sum warp partials, sigmoid, zero diagonal ----
        if (tid < EG) {
            float s = 0.f;
            #pragma unroll
            for (int w = 0; w < 8; ++w) s += sEp[w * EG + tid];
            int gi = i0 + (tid >> 4), gj = j0 + (tid & 15);
            sE[tid] = (gi == gj) ? 0.f : sigmf(s + binf_v);
        }
        __syncthreads();

        // ---- m_i accumulation (thread owns column tid) ----
        {
            int t = tid;
            #pragma unroll 8
            for (int e = 0; e < EG; ++e)
                sMi[(e >> 4) * MDIM + t] = fmaf(sA[e * SAPAD + t], sE[e], sMi[(e >> 4) * MDIM + t]);
        }
        __syncthreads();

        // ---- GEMM2: b1 = silu(m @ Wx0 + bx0) -> sA (rounded) ----
        gemm64x256_hmma(Wx0, sA, sW, acc, tid);
        #pragma unroll
        for (int mt = 0; mt < 4; ++mt)
            #pragma unroll
            for (int nt = 0; nt < 4; ++nt)
                #pragma unroll
                for (int c = 0; c < 4; ++c) {
                    int row = mt * 16 + wg + ((c >= 2) ? 8 : 0);
                    int col = wn0 + nt * 8 + wtg * 2 + (c & 1);
                    sA[row * SAPAD + col] = tf32r(siluf(acc[mt][nt][c] + sBx0[col]));
                }
        __syncthreads();

        // ---- GEMM3: b2 = silu(b1 @ Wx1 + bx1), px folded in-register ----
        gemm64x256_hmma(Wx1, sA, sW, acc, tid);
        {
            // activate in place
            #pragma unroll
            for (int mt = 0; mt < 4; ++mt)
                #pragma unroll
                for (int nt = 0; nt < 4; ++nt)
                    #pragma unroll
                    for (int c = 0; c < 4; ++c) {
                        int col = wn0 + nt * 8 + wtg * 2 + (c & 1);
                        acc[mt][nt][c] = siluf(acc[mt][nt][c] + sBx1[col]);
                    }
            // px partials per head (sPxW aliases staging buffer; GEMM3 staging is complete)
            #pragma unroll
            for (int hh = 0; hh < 8; ++hh) {
                float pxp[4][2];
                #pragma unroll
                for (int mt = 0; mt < 4; ++mt) { pxp[mt][0] = 0.f; pxp[mt][1] = 0.f; }
                #pragma unroll
                for (int nt = 0; nt < 4; ++nt)
                    #pragma unroll
                    for (int lo = 0; lo < 2; ++lo) {
                        int col = wn0 + nt * 8 + wtg * 2 + lo;
                        float wv = sWxo[col * 8 + hh];
                        #pragma unroll
                        for (int mt = 0; mt < 4; ++mt) {
                            pxp[mt][0] = fmaf(acc[mt][nt][lo],     wv, pxp[mt][0]);
                            pxp[mt][1] = fmaf(acc[mt][nt][2 + lo], wv, pxp[mt][1]);
                        }
                    }
                #pragma unroll
                for (int mt = 0; mt < 4; ++mt)
                    #pragma unroll
                    for (int hi = 0; hi < 2; ++hi) {
                        pxp[mt][hi] += __shfl_xor_sync(0xffffffffu, pxp[mt][hi], 1);
                        pxp[mt][hi] += __shfl_xor_sync(0xffffffffu, pxp[mt][hi], 2);
                    }
                if (wtg == 0) {
                    #pragma unroll
                    for (int mt = 0; mt < 4; ++mt)
                        #pragma unroll
                        for (int hi = 0; hi < 2; ++hi)
                            sPxW[wid * (EG * NH) + (mt * 16 + wg + 8 * hi) * 8 + hh] = pxp[mt][hi];
                }
            }
        }
        __syncthreads();

        // ---- px final: sum warp partials + bias, zero diagonal ----
        #pragma unroll
        for (int rep = 0; rep < 2; ++rep) {
            int q = tid + rep * NTHREADS;
            int row = q >> 3, hh = q & 7;
            float s = sBxo[hh];
            #pragma unroll
            for (int w = 0; w < 8; ++w) s += sPxW[w * (EG * NH) + q];
            int gi = i0 + (row >> 4), gj = j0 + (row & 15);
            sPx[q] = (gi == gj) ? 0.f : s;
        }
        __syncthreads();

        // ---- shift accumulation ----
        if (tid < 96) {
            int ti = tid / 24, r = tid % 24, hh = r / 3, d = r % 3;
            float a = 0.f;
            #pragma unroll
            for (int tj = 0; tj < TJ; ++tj) {
                int e = ti * 16 + tj;
                float sq = sSqn[e * 8 + hh];
                float nrm = sqrtf(sq + 1e-8f) + 1.0f;
                float dn = sXj[tj * 24 + hh * 3 + d] - sXi[ti * 24 + hh * 3 + d];
                a = fmaf(sPx[e * 8 + hh], __fdividef(dn, nrm), a);
            }
            sShift[tid] += a;
        }
    }
    __syncthreads();

    // ---- write partials ----
    {
        int t = tid;
        #pragma unroll
        for (int ti = 0; ti < TI; ++ti)
            g_mi_part[(js * NN + i0 + ti) * MDIM + t] = sMi[ti * MDIM + t];
    }
    if (tid < 96) {
        int ti = tid / 24, r = tid % 24;
        g_shift_part[(js * NN + i0 + ti) * 24 + r] = sShift[tid];
    }
}

// ============================================================
// Kernel 3: x_new = x + (sum_js shift_part) / (N-1)
// ============================================================
__global__ void finalize_x_kernel(const float* __restrict__ x, float* __restrict__ out)
{
    int idx = blockIdx.x * 256 + threadIdx.x;
    if (idx < NN * NH * 3) {
        float s = 0.f;
        #pragma unroll
        for (int js = 0; js < JS; ++js) s += g_shift_part[js * NN * 24 + idx];
        out[idx] = x[idx] + s * (1.0f / (float)(NN - 1));
    }
}

// ============================================================
// Kernel 4: phi_h  (2 nodes per block for occupancy)
// ============================================================
#define NPB 2
__global__ void __launch_bounds__(256) h_kernel(
    const float* __restrict__ h,
    const float* __restrict__ Wh0, const float* __restrict__ bh0,
    const float* __restrict__ Wh1, const float* __restrict__ bh1,
    const float* __restrict__ Who, const float* __restrict__ bho,
    float* __restrict__ out)
{
    __shared__ float sin_s[NPB][384];
    __shared__ float s1[NPB][256];
    __shared__ float s2[NPB][256];
    int tid = threadIdx.x;
    int nb = blockIdx.x * NPB;

    for (int t = tid; t < NPB * 256; t += 256) {
        int nn = t >> 8, c = t & 255;
        float mi = 0.f;
        #pragma unroll
        for (int js = 0; js < JS; ++js)
            mi += g_mi_part[(js * NN + nb + nn) * MDIM + c];
        sin_s[nn][c] = mi;
    }
    for (int t = tid; t < NPB * 128; t += 256) {
        int nn = t >> 7, c = t & 127;
        sin_s[nn][256 + c] = h[(nb + nn) * 128 + c];
    }
    __syncthreads();
    {
        float acc[NPB];
        #pragma unroll
        for (int nn = 0; nn < NPB; ++nn) acc[nn] = 0.f;
        for (int k = 0; k < 384; ++k) {
            float w = Wh0[k * 256 + tid];
            #pragma unroll
            for (int nn = 0; nn < NPB; ++nn) acc[nn] = fmaf(sin_s[nn][k], w, acc[nn]);
        }
        float b = bh0[tid];
        #pragma unroll
        for (int nn = 0; nn < NPB; ++nn) s1[nn][tid] = siluf(acc[nn] + b);
    }
    __syncthreads();
    {
        float acc[NPB];
        #pragma unroll
        for (int nn = 0; nn < NPB; ++nn) acc[nn] = 0.f;
        for (int k = 0; k < 256; ++k) {
            float w = Wh1[k * 256 + tid];
            #pragma unroll
            for (int nn = 0; nn < NPB; ++nn) acc[nn] = fmaf(s1[nn][k], w, acc[nn]);
        }
        float b = bh1[tid];
        #pragma unroll
        for (int nn = 0; nn < NPB; ++nn) s2[nn][tid] = siluf(acc[nn] + b);
    }
    __syncthreads();
    if (tid < 128) {
        float acc[NPB];
        #pragma unroll
        for (int nn = 0; nn < NPB; ++nn) acc[nn] = 0.f;
        for (int k = 0; k < 256; ++k) {
            float w = Who[k * 128 + tid];
            #pragma unroll
            for (int nn = 0; nn < NPB; ++nn) acc[nn] = fmaf(s2[nn][k], w, acc[nn]);
        }
        float b = bho[tid];
        #pragma unroll
        for (int nn = 0; nn < NPB; ++nn)
            out[NN * NH * 3 + (nb + nn) * 128 + tid] = h[(nb + nn) * 128 + tid] + acc[nn] + b;
    }
}

// ============================================================
extern "C" void kernel_launch(void* const* d_in, const int* in_sizes, int n_in,
                              void* d_out, int out_size)
{
    const float* x    = (const float*)d_in[0];
    const float* h    = (const float*)d_in[1];
    const float* We0  = (const float*)d_in[2];
    const float* be0  = (const float*)d_in[3];
    const float* We1  = (const float*)d_in[4];
    const float* be1  = (const float*)d_in[5];
    const float* Winf = (const float*)d_in[6];
    const float* binf = (const float*)d_in[7];
    const float* Wx0  = (const float*)d_in[8];
    const float* bx0  = (const float*)d_in[9];
    const float* Wx1  = (const float*)d_in[10];
    const float* bx1  = (const float*)d_in[11];
    const float* Wxo  = (const float*)d_in[12];
    const float* bxo  = (const float*)d_in[13];
    const float* Wh0  = (const float*)d_in[14];
    const float* bh0  = (const float*)d_in[15];
    const float* Wh1  = (const float*)d_in[16];
    const float* bh1  = (const float*)d_in[17];
    const float* Who  = (const float*)d_in[18];
    const float* bho  = (const float*)d_in[19];
    float* out = (float*)d_out;

    node_pre_kernel<<<NN, 256>>>(x, h, We0);

    const int smem_floats =
        EG * SAPAD + UNION_FLOATS + MDIM * 8 +
        MDIM * 5 + 8 + TI * MDIM + EG * NH + 96 + 384 + EG + EG * NH + 96;
    const int smem_bytes = smem_floats * 4;   // 109,600 B -> 2 CTAs/SM
    static int attr_set = 0;
    if (!attr_set) {
        cudaFuncSetAttribute(edge_kernel, cudaFuncAttributeMaxDynamicSharedMemorySize, smem_bytes);
        attr_set = 1;
    }
    edge_kernel<<<dim3(NN / TI, JS), NTHREADS, smem_bytes>>>(
        x, We0, be0, We1, be1, Winf, binf, Wx0, bx0, Wx1, bx1, Wxo, bxo);

    finalize_x_kernel<<<(NN * NH * 3 + 255) / 256, 256>>>(x, out);

    h_kernel<<<NN / NPB, 256>>>(h, Wh0, bh0, Wh1, bh1, Who, bho, out);
}

// round 17
// speedup vs baseline: 2.0063x; 1.7793x over previous
#include <cuda_runtime.h>
#include <cuda_fp16.h>
#include <cstdint>
#include <cstring>

#define NN   512
#define HDIM 128
#define NH   8
#define MDIM 256
#define TI   4
#define TJ   16
#define EG   64      // edges per tile = TI*TJ
#define JS   4       // j splits
#define NTHREADS 256
#define SAPAD16 132  // uint32 words per edge row (128 data + 4 pad): A-frag banks 4g+tg
#define SWPAD16 20   // uint32 words per n row per stage (16 data + 4 pad)
#define NCHUNK 8     // 8 chunks of 32-k per GEMM
#define UNION_WORDS 5120   // staging(256*20) ∪ sPxW(4096 fl) ∪ sEp@4224(512 fl)

// ---- scratch (device globals; no allocation allowed) ----
__device__ float g_A[NN * MDIM];                 // hc @ We0[8:200]
__device__ float g_B[NN * MDIM];                 // hc @ We0[200:392]
__device__ __align__(16) uint32_t g_Wpk[3 * MDIM * (MDIM / 2)];  // [mat][n][kpair] packed half2
__device__ float g_mi_part[JS * NN * MDIM];
__device__ float g_shift_part[JS * NN * NH * 3];

__device__ __forceinline__ float siluf(float v) {
    return __fdividef(v, 1.0f + __expf(-v));
}
__device__ __forceinline__ float sigmf(float v) {
    return __fdividef(1.0f, 1.0f + __expf(-v));
}
__device__ __forceinline__ uint32_t packh2(float lo, float hi) {
    __half2 h = __floats2half2_rn(lo, hi);
    uint32_t r; memcpy(&r, &h, 4); return r;
}
__device__ __forceinline__ float2 unpackh2(uint32_t w) {
    __half2 h; memcpy(&h, &w, 4); return __half22float2(h);
}

__device__ __forceinline__ void mma_f16(float* d,
    uint32_t a0, uint32_t a1, uint32_t a2, uint32_t a3,
    uint32_t b0, uint32_t b1)
{
    asm volatile(
        "mma.sync.aligned.m16n8k16.row.col.f32.f16.f16.f32 "
        "{%0,%1,%2,%3}, {%4,%5,%6,%7}, {%8,%9}, {%0,%1,%2,%3};\n"
        : "+f"(d[0]), "+f"(d[1]), "+f"(d[2]), "+f"(d[3])
        : "r"(a0), "r"(a1), "r"(a2), "r"(a3), "r"(b0), "r"(b1));
}

// ============================================================
// Kernel 0: pack weights -> g_Wpk[mat][n][kpair] (half2 pairs along k)
// grid 3*8 blocks, 256 threads; smem transpose for coalescing both ways
// ============================================================
__global__ void __launch_bounds__(256) prep_weights_kernel(
    const float* __restrict__ We1, const float* __restrict__ Wx0,
    const float* __restrict__ Wx1)
{
    __shared__ float s[256][33];
    int g = blockIdx.x >> 3;
    int n0 = (blockIdx.x & 7) * 32;
    int tid = threadIdx.x;
    const float* W = (g == 0) ? We1 : ((g == 1) ? Wx0 : Wx1);
    #pragma unroll 4
    for (int it = 0; it < 32; ++it) {
        int row = it * 8 + (tid >> 5);
        s[row][tid & 31] = W[row * 256 + n0 + (tid & 31)];
    }
    __syncthreads();
    int nl = tid >> 7;          // 0..1
    int kp = tid & 127;
    #pragma unroll
    for (int p = 0; p < 16; ++p) {
        int n = nl * 16 + p;
        g_Wpk[g * 32768 + (n0 + n) * 128 + kp] = packh2(s[2 * kp][n], s[2 * kp + 1][n]);
    }
}

// ============================================================
// Kernel 1: per-node hc = [h, sqh]; A = hc@We0[8:200], B = hc@We0[200:392]
// ============================================================
__global__ void __launch_bounds__(256) node_pre_kernel(
    const float* __restrict__ x, const float* __restrict__ h,
    const float* __restrict__ We0)
{
    __shared__ float hc[192];
    __shared__ float sx[24];
    int n = blockIdx.x;
    int tid = threadIdx.x;
    if (tid < 24)  sx[tid] = x[n * 24 + tid];
    if (tid < 128) hc[tid] = h[n * 128 + tid];
    __syncthreads();
    if (tid < 64) {
        int h1 = tid >> 3, h2 = tid & 7;
        float s = 0.f;
        #pragma unroll
        for (int d = 0; d < 3; ++d) {
            float dx = sx[h1 * 3 + d] - sx[h2 * 3 + d];
            s += dx * dx;
        }
        hc[128 + tid] = s;
    }
    __syncthreads();
    float a = 0.f, b = 0.f;
    for (int k = 0; k < 192; ++k) {
        float v = hc[k];
        a = fmaf(v, We0[(8 + k) * 256 + tid], a);
        b = fmaf(v, We0[(200 + k) * 256 + tid], b);
    }
    g_A[n * 256 + tid] = a;
    g_B[n * 256 + tid] = b;
}

// ============================================================
// fp16 HMMA GEMM: acc = sA16[64 x 256 fp16] @ Wpk^T  (fp32 accum)
// 8 warps, warp w owns cols [32w, 32w+32). m16n8k16, 16 k-steps.
// Weight staging: pure uint4 copy from pre-packed global, reg-prefetched.
// ============================================================
__device__ __forceinline__ void gemm64x256_h(
    const uint32_t* __restrict__ Wpk, const uint32_t* sIn, uint32_t* sW,
    float acc[4][4][4], int tid)
{
    const int w = tid >> 5;
    const int lane = tid & 31;
    const int g = lane >> 2, tg = lane & 3;
    const int n0w = w * 32;

    #pragma unroll
    for (int mt = 0; mt < 4; ++mt)
        #pragma unroll
        for (int nt = 0; nt < 4; ++nt)
            #pragma unroll
            for (int c = 0; c < 4; ++c) acc[mt][nt][c] = 0.f;

    const uint4* src = (const uint4*)Wpk;   // [n][32 uint4]
    uint4 pre[4];
    #pragma unroll
    for (int j = 0; j < 4; ++j) pre[j] = src[tid * 32 + j];

    for (int c = 0; c < NCHUNK; ++c) {
        __syncthreads();
        #pragma unroll
        for (int j = 0; j < 4; ++j)
            *(uint4*)(sW + tid * SWPAD16 + j * 4) = pre[j];
        __syncthreads();
        if (c + 1 < NCHUNK) {
            #pragma unroll
            for (int j = 0; j < 4; ++j)
                pre[j] = src[tid * 32 + (c + 1) * 4 + j];
        }
        #pragma unroll
        for (int ks = 0; ks < 2; ++ks) {
            const int kb8 = c * 16 + ks * 8;   // word offset into sA16 rows
            uint32_t a[4][4], b[4][2];
            #pragma unroll
            for (int mt = 0; mt < 4; ++mt) {
                const uint32_t* base = sIn + (mt * 16 + g) * SAPAD16 + kb8 + tg;
                a[mt][0] = base[0];
                a[mt][1] = base[8 * SAPAD16];
                a[mt][2] = base[4];
                a[mt][3] = base[8 * SAPAD16 + 4];
            }
            #pragma unroll
            for (int nt = 0; nt < 4; ++nt) {
                const uint32_t* bb = sW + (n0w + nt * 8 + g) * SWPAD16 + ks * 8 + tg;
                b[nt][0] = bb[0];
                b[nt][1] = bb[4];
            }
            #pragma unroll
            for (int mt = 0; mt < 4; ++mt)
                #pragma unroll
                for (int nt = 0; nt < 4; ++nt)
                    mma_f16(acc[mt][nt], a[mt][0], a[mt][1], a[mt][2], a[mt][3],
                            b[nt][0], b[nt][1]);
        }
    }
    __syncthreads();
}

// ============================================================
// Kernel 2: fused edge pipeline. grid (NN/TI, JS), 256 threads, 2 CTAs/SM
// ============================================================
__global__ void __launch_bounds__(NTHREADS, 2) edge_kernel(
    const float* __restrict__ x,
    const float* __restrict__ We0, const float* __restrict__ be0,
    const float* __restrict__ be1,
    const float* __restrict__ Winf, const float* __restrict__ binf,
    const float* __restrict__ bx0, const float* __restrict__ bx1,
    const float* __restrict__ Wxo, const float* __restrict__ bxo)
{
    extern __shared__ float sm[];
    uint32_t* sA16  = (uint32_t*)sm;                 // 64*132 words
    float* sU    = sm + EG * SAPAD16;                // UNION_WORDS
    uint32_t* sW = (uint32_t*)sU;                    // staging (GEMM phases)
    float* sPxW  = sU;                               // px partials (epi3 phase)
    float* sEp   = sU + 4224;                        // e partials (epi1 phase)
    float* sWxo  = sU + UNION_WORDS;                 // 256*8
    float* sWinf = sWxo + MDIM * 8;                  // 256
    float* sBe0  = sWinf + MDIM;                     // 256
    float* sBe1  = sBe0 + MDIM;                      // 256
    float* sBx0  = sBe1 + MDIM;                      // 256
    float* sBx1  = sBx0 + MDIM;                      // 256
    float* sBxo  = sBx1 + MDIM;                      // 8
    float* sMi   = sBxo + 8;                         // 4*256
    float* sSqn  = sMi + TI * MDIM;                  // 64*8
    float* sXi   = sSqn + EG * NH;                   // 96
    float* sXj   = sXi + 96;                         // 384
    float* sE    = sXj + 384;                        // 64
    float* sPx   = sE + EG;                          // 64*8
    float* sShift = sPx + EG * NH;                   // 96

    int tid = threadIdx.x;
    int i0 = blockIdx.x * TI;
    int js = blockIdx.y;
    const int wid = tid >> 5;
    const int wlane = tid & 31;
    const int wg = wlane >> 2, wtg = wlane & 3;
    const int wn0 = wid * 32;
    const int q = tid & 127;      // column-pair owned in layer1/m_i
    const int eh = tid >> 7;      // edge-half group

    // ---- per-thread constants: We0 rows 0..7 at cols 2q,2q+1 ----
    float2 w0s2[8];
    #pragma unroll
    for (int hh = 0; hh < 8; ++hh)
        w0s2[hh] = *(const float2*)(We0 + hh * MDIM + 2 * q);

    for (int t = tid; t < MDIM * 8; t += NTHREADS) sWxo[t] = Wxo[t];
    sWinf[tid] = Winf[tid];
    sBe0[tid] = be0[tid];
    sBe1[tid] = be1[tid];
    sBx0[tid] = bx0[tid];
    sBx1[tid] = bx1[tid];
    if (tid < 8) sBxo[tid] = bxo[tid];
    for (int t = tid; t < TI * MDIM; t += NTHREADS) sMi[t] = 0.f;
    if (tid < 96) { sShift[tid] = 0.f; sXi[tid] = x[i0 * 24 + tid]; }
    float binf_v = binf[0];

    const int NJT = (NN / JS) / TJ;   // 8
    for (int jt = 0; jt < NJT; ++jt) {
        int j0 = js * (NN / JS) + jt * TJ;
        __syncthreads();
        for (int t = tid; t < TJ * 24; t += NTHREADS) sXj[t] = x[j0 * 24 + t];
        __syncthreads();

        // ---- sqn tile ----
        for (int qq = tid; qq < EG * NH; qq += NTHREADS) {
            int e = qq >> 3, hh = qq & 7;
            int ti = e >> 4, tj = e & 15;
            float s = 0.f;
            #pragma unroll
            for (int d = 0; d < 3; ++d) {
                float dx = sXj[tj * 24 + hh * 3 + d] - sXi[ti * 24 + hh * 3 + d];
                s += dx * dx;
            }
            sSqn[qq] = s;
        }
        __syncthreads();

        // ---- layer 1: a1 = silu(A[j] + B[i] + be0 + sqn@We0[0:8]) -> packed fp16 ----
        {
            float2 be0p = *(const float2*)(sBe0 + 2 * q);
            float2 bvals[2];
            #pragma unroll
            for (int t2 = 0; t2 < 2; ++t2) {
                float2 bv = *(const float2*)(g_B + (i0 + eh * 2 + t2) * MDIM + 2 * q);
                bvals[t2].x = bv.x + be0p.x;
                bvals[t2].y = bv.y + be0p.y;
            }
            float2 avals[TJ];
            #pragma unroll
            for (int tj = 0; tj < TJ; ++tj)
                avals[tj] = *(const float2*)(g_A + (j0 + tj) * MDIM + 2 * q);
            #pragma unroll
            for (int e2 = 0; e2 < 32; ++e2) {
                int e = eh * 32 + e2;
                int t2 = e2 >> 4, tj = e2 & 15;
                float v0 = avals[tj].x + bvals[t2].x;
                float v1 = avals[tj].y + bvals[t2].y;
                #pragma unroll
                for (int hh = 0; hh < 8; ++hh) {
                    float sq = sSqn[e * 8 + hh];
                    v0 = fmaf(sq, w0s2[hh].x, v0);
                    v1 = fmaf(sq, w0s2[hh].y, v1);
                }
                sA16[e * SAPAD16 + q] = packh2(siluf(v0), siluf(v1));
            }
        }
        __syncthreads();

        float acc[4][4][4];

        // ---- GEMM1: m = silu(a1 @ We1 + be1) -> sA16; fold e-gate partials ----
        gemm64x256_h(g_Wpk, sA16, sW, acc, tid);
        {
            float ep[4][2];
            #pragma unroll
            for (int mt = 0; mt < 4; ++mt) { ep[mt][0] = 0.f; ep[mt][1] = 0.f; }
            #pragma unroll
            for (int mt = 0; mt < 4; ++mt)
                #pragma unroll
                for (int nt = 0; nt < 4; ++nt)
                    #pragma unroll
                    for (int hi = 0; hi < 2; ++hi) {
                        int row = mt * 16 + wg + 8 * hi;
                        int col0 = wn0 + nt * 8 + wtg * 2;
                        float2 wi = *(const float2*)(sWinf + col0);
                        float v0 = siluf(acc[mt][nt][2 * hi] + sBe1[col0]);
                        float v1 = siluf(acc[mt][nt][2 * hi + 1] + sBe1[col0 + 1]);
                        ep[mt][hi] = fmaf(v0, wi.x, fmaf(v1, wi.y, ep[mt][hi]));
                        sA16[row * SAPAD16 + (col0 >> 1)] = packh2(v0, v1);
                    }
            #pragma unroll
            for (int mt = 0; mt < 4; ++mt)
                #pragma unroll
                for (int hi = 0; hi < 2; ++hi) {
                    ep[mt][hi] += __shfl_xor_sync(0xffffffffu, ep[mt][hi], 1);
                    ep[mt][hi] += __shfl_xor_sync(0xffffffffu, ep[mt][hi], 2);
                }
            if (wtg == 0) {
                #pragma unroll
                for (int mt = 0; mt < 4; ++mt)
                    #pragma unroll
                    for (int hi = 0; hi < 2; ++hi)
                        sEp[wid * EG + mt * 16 + wg + 8 * hi] = ep[mt][hi];
            }
        }
        __syncthreads();

        // ---- e final ----
        if (tid < EG) {
            float s = 0.f;
            #pragma unroll
            for (int w = 0; w < 8; ++w) s += sEp[w * EG + tid];
            int gi = i0 + (tid >> 4), gj = j0 + (tid & 15);
            sE[tid] = (gi == gj) ? 0.f : sigmf(s + binf_v);
        }
        __syncthreads();

        // ---- m_i accumulation: thread owns (col-pair q, edge-half eh) ----
        // eh splits edges into ti{0,1} vs ti{2,3} -> unique (ti,col) writers.
        {
            #pragma unroll 8
            for (int e2 = 0; e2 < 32; ++e2) {
                int e = eh * 32 + e2;
                float2 mv = unpackh2(sA16[e * SAPAD16 + q]);
                float ee = sE[e];
                int ti = e >> 4;
                sMi[ti * MDIM + 2 * q]     = fmaf(mv.x, ee, sMi[ti * MDIM + 2 * q]);
                sMi[ti * MDIM + 2 * q + 1] = fmaf(mv.y, ee, sMi[ti * MDIM + 2 * q + 1]);
            }
        }
        __syncthreads();

        // ---- GEMM2: b1 = silu(m @ Wx0 + bx0) -> sA16 ----
        gemm64x256_h(g_Wpk + 32768, sA16, sW, acc, tid);
        #pragma unroll
        for (int mt = 0; mt < 4; ++mt)
            #pragma unroll
            for (int nt = 0; nt < 4; ++nt)
                #pragma unroll
                for (int hi = 0; hi < 2; ++hi) {
                    int row = mt * 16 + wg + 8 * hi;
                    int col0 = wn0 + nt * 8 + wtg * 2;
                    float v0 = siluf(acc[mt][nt][2 * hi] + sBx0[col0]);
                    float v1 = siluf(acc[mt][nt][2 * hi + 1] + sBx0[col0 + 1]);
                    sA16[row * SAPAD16 + (col0 >> 1)] = packh2(v0, v1);
                }
        __syncthreads();

        // ---- GEMM3: b2 = silu(b1 @ Wx1 + bx1), px folded in-register ----
        gemm64x256_h(g_Wpk + 2 * 32768, sA16, sW, acc, tid);
        {
            #pragma unroll
            for (int mt = 0; mt < 4; ++mt)
                #pragma unroll
                for (int nt = 0; nt < 4; ++nt)
                    #pragma unroll
                    for (int c = 0; c < 4; ++c) {
                        int col = wn0 + nt * 8 + wtg * 2 + (c & 1);
                        acc[mt][nt][c] = siluf(acc[mt][nt][c] + sBx1[col]);
                    }
            #pragma unroll
            for (int hh = 0; hh < 8; ++hh) {
                float pxp[4][2];
                #pragma unroll
                for (int mt = 0; mt < 4; ++mt) { pxp[mt][0] = 0.f; pxp[mt][1] = 0.f; }
                #pragma unroll
                for (int nt = 0; nt < 4; ++nt)
                    #pragma unroll
                    for (int lo = 0; lo < 2; ++lo) {
                        int col = wn0 + nt * 8 + wtg * 2 + lo;
                        float wv = sWxo[col * 8 + hh];
                        #pragma unroll
                        for (int mt = 0; mt < 4; ++mt) {
                            pxp[mt][0] = fmaf(acc[mt][nt][lo],     wv, pxp[mt][0]);
                            pxp[mt][1] = fmaf(acc[mt][nt][2 + lo], wv, pxp[mt][1]);
                        }
                    }
                #pragma unroll
                for (int mt = 0; mt < 4; ++mt)
                    #pragma unroll
                    for (int hi = 0; hi < 2; ++hi) {
                        pxp[mt][hi] += __shfl_xor_sync(0xffffffffu, pxp[mt][hi], 1);
                        pxp[mt][hi] += __shfl_xor_sync(0xffffffffu, pxp[mt][hi], 2);
                    }
                if (wtg == 0) {
                    #pragma unroll
                    for (int mt = 0; mt < 4; ++mt)
                        #pragma unroll
                        for (int hi = 0; hi < 2; ++hi)
                            sPxW[wid * (EG * NH) + (mt * 16 + wg + 8 * hi) * 8 + hh] = pxp[mt][hi];
                }
            }
        }
        __syncthreads();

        // ---- px final ----
        #pragma unroll
        for (int rep = 0; rep < 2; ++rep) {
            int qq = tid + rep * NTHREADS;
            int row = qq >> 3, hh = qq & 7;
            float s = sBxo[hh];
            #pragma unroll
            for (int w = 0; w < 8; ++w) s += sPxW[w * (EG * NH) + qq];
            int gi = i0 + (row >> 4), gj = j0 + (row & 15);
            sPx[qq] = (gi == gj) ? 0.f : s;
        }
        __syncthreads();

        // ---- shift accumulation ----
        if (tid < 96) {
            int ti = tid / 24, r = tid % 24, hh = r / 3, d = r % 3;
            float a = 0.f;
            #pragma unroll
            for (int tj = 0; tj < TJ; ++tj) {
                int e = ti * 16 + tj;
                float sq = sSqn[e * 8 + hh];
                float nrm = sqrtf(sq + 1e-8f) + 1.0f;
                float dn = sXj[tj * 24 + hh * 3 + d] - sXi[ti * 24 + hh * 3 + d];
                a = fmaf(sPx[e * 8 + hh], __fdividef(dn, nrm), a);
            }
            sShift[tid] += a;
        }
    }
    __syncthreads();

    // ---- write partials ----
    {
        int t = tid;
        #pragma unroll
        for (int ti = 0; ti < TI; ++ti)
            g_mi_part[(js * NN + i0 + ti) * MDIM + t] = sMi[ti * MDIM + t];
    }
    if (tid < 96) {
        int ti = tid / 24, r = tid % 24;
        g_shift_part[(js * NN + i0 + ti) * 24 + r] = sShift[tid];
    }
}

// ============================================================
// Kernel 3: x_new = x + (sum_js shift_part) / (N-1)
// ============================================================
__global__ void finalize_x_kernel(const float* __restrict__ x, float* __restrict__ out)
{
    int idx = blockIdx.x * 256 + threadIdx.x;
    if (idx < NN * NH * 3) {
        float s = 0.f;
        #pragma unroll
        for (int js = 0; js < JS; ++js) s += g_shift_part[js * NN * 24 + idx];
        out[idx] = x[idx] + s * (1.0f / (float)(NN - 1));
    }
}

// ============================================================
// Kernel 4: phi_h  (2 nodes per block)
// ============================================================
#define NPB 2
__global__ void __launch_bounds__(256) h_kernel(
    const float* __restrict__ h,
    const float* __restrict__ Wh0, const float* __restrict__ bh0,
    const float* __restrict__ Wh1, const float* __restrict__ bh1,
    const float* __restrict__ Who, const float* __restrict__ bho,
    float* __restrict__ out)
{
    __shared__ float sin_s[NPB][384];
    __shared__ float s1[NPB][256];
    __shared__ float s2[NPB][256];
    int tid = threadIdx.x;
    int nb = blockIdx.x * NPB;

    for (int t = tid; t < NPB * 256; t += 256) {
        int nn = t >> 8, c = t & 255;
        float mi = 0.f;
        #pragma unroll
        for (int js = 0; js < JS; ++js)
            mi += g_mi_part[(js * NN + nb + nn) * MDIM + c];
        sin_s[nn][c] = mi;
    }
    for (int t = tid; t < NPB * 128; t += 256) {
        int nn = t >> 7, c = t & 127;
        sin_s[nn][256 + c] = h[(nb + nn) * 128 + c];
    }
    __syncthreads();
    {
        float acc[NPB];
        #pragma unroll
        for (int nn = 0; nn < NPB; ++nn) acc[nn] = 0.f;
        for (int k = 0; k < 384; ++k) {
            float w = Wh0[k * 256 + tid];
            #pragma unroll
            for (int nn = 0; nn < NPB; ++nn) acc[nn] = fmaf(sin_s[nn][k], w, acc[nn]);
        }
        float b = bh0[tid];
        #pragma unroll
        for (int nn = 0; nn < NPB; ++nn) s1[nn][tid] = siluf(acc[nn] + b);
    }
    __syncthreads();
    {
        float acc[NPB];
        #pragma unroll
        for (int nn = 0; nn < NPB; ++nn) acc[nn] = 0.f;
        for (int k = 0; k < 256; ++k) {
            float w = Wh1[k * 256 + tid];
            #pragma unroll
            for (int nn = 0; nn < NPB; ++nn) acc[nn] = fmaf(s1[nn][k], w, acc[nn]);
        }
        float b = bh1[tid];
        #pragma unroll
        for (int nn = 0; nn < NPB; ++nn) s2[nn][tid] = siluf(acc[nn] + b);
    }
    __syncthreads();
    if (tid < 128) {
        float acc[NPB];
        #pragma unroll
        for (int nn = 0; nn < NPB; ++nn) acc[nn] = 0.f;
        for (int k = 0; k < 256; ++k) {
            float w = Who[k * 128 + tid];
            #pragma unroll
            for (int nn = 0; nn < NPB; ++nn) acc[nn] = fmaf(s2[nn][k], w, acc[nn]);
        }
        float b = bho[tid];
        #pragma unroll
        for (int nn = 0; nn < NPB; ++nn)
            out[NN * NH * 3 + (nb + nn) * 128 + tid] = h[(nb + nn) * 128 + tid] + acc[nn] + b;
    }
}

// ============================================================
extern "C" void kernel_launch(void* const* d_in, const int* in_sizes, int n_in,
                              void* d_out, int out_size)
{
    const float* x    = (const float*)d_in[0];
    const float* h    = (const float*)d_in[1];
    const float* We0  = (const float*)d_in[2];
    const float* be0  = (const float*)d_in[3];
    const float* We1  = (const float*)d_in[4];
    const float* be1  = (const float*)d_in[5];
    const float* Winf = (const float*)d_in[6];
    const float* binf = (const float*)d_in[7];
    const float* Wx0  = (const float*)d_in[8];
    const float* bx0  = (const float*)d_in[9];
    const float* Wx1  = (const float*)d_in[10];
    const float* bx1  = (const float*)d_in[11];
    const float* Wxo  = (const float*)d_in[12];
    const float* bxo  = (const float*)d_in[13];
    const float* Wh0  = (const float*)d_in[14];
    const float* bh0  = (const float*)d_in[15];
    const float* Wh1  = (const float*)d_in[16];
    const float* bh1  = (const float*)d_in[17];
    const float* Who  = (const float*)d_in[18];
    const float* bho  = (const float*)d_in[19];
    float* out = (float*)d_out;

    prep_weights_kernel<<<24, 256>>>(We1, Wx0, Wx1);
    node_pre_kernel<<<NN, 256>>>(x, h, We0);

    const int smem_floats =
        EG * SAPAD16 + UNION_WORDS + MDIM * 8 +
        MDIM * 5 + 8 + TI * MDIM + EG * NH + 96 + 384 + EG + EG * NH + 96;
    const int smem_bytes = smem_floats * 4;   // ~78.4 KB -> 2 CTAs/SM
    static int attr_set = 0;
    if (!attr_set) {
        cudaFuncSetAttribute(edge_kernel, cudaFuncAttributeMaxDynamicSharedMemorySize, smem_bytes);
        attr_set = 1;
    }
    edge_kernel<<<dim3(NN / TI, JS), NTHREADS, smem_bytes>>>(
        x, We0, be0, be1, Winf, binf, bx0, bx1, Wxo, bxo);

    finalize_x_kernel<<<(NN * NH * 3 + 255) / 256, 256>>>(x, out);

    h_kernel<<<NN / NPB, 256>>>(h, Wh0, bh0, Wh1, bh1, Who, bho, out);
}